// round 9
// baseline (speedup 1.0000x reference)
#include <cuda_runtime.h>
#include <cuda_fp16.h>
#include <cstdint>

#define BB 4096
#define DD 256
#define HH 1024
#define PP 10
#define NE (PP*BB*DD)
#define NWORDS (NE/32)

// ---------------- device scratch ----------------
__device__ uint32_t g_ebits[4][NWORDS];
__device__ float    g_S[4][BB*HH];
__device__ float    g_W2t[DD*HH];
__device__ float    g_bias1[4*HH];
__device__ uint32_t g_hh[BB*HH/2];      // h as half2
__device__ uint32_t g_zh[BB*DD/2];      // z as half2
__device__ uint32_t g_xh[BB*DD/2];      // x as half2
__device__ uint32_t g_W1p[128*HH];      // W1 k-paired half2
__device__ uint32_t g_W2p[512*DD];      // W2 k-paired half2
__device__ float    g_accz[BB*DD];
__device__ float    g_accd[BB];

// ---------------- Threefry-2x32 ----------------
__device__ __forceinline__ void tf_dev(unsigned int k0, unsigned int k1,
                                       unsigned int x0, unsigned int x1,
                                       unsigned int& o0, unsigned int& o1) {
    unsigned int k2 = k0 ^ k1 ^ 0x1BD11BDAu;
#define TFR(r) { x0 += x1; x1 = __funnelshift_l(x1, x1, r); x1 ^= x0; }
    x0 += k0; x1 += k1;          TFR(13) TFR(15) TFR(26) TFR(6)
    x0 += k1; x1 += k2 + 1u;     TFR(17) TFR(29) TFR(16) TFR(24)
    x0 += k2; x1 += k0 + 2u;     TFR(13) TFR(15) TFR(26) TFR(6)
    x0 += k0; x1 += k1 + 3u;     TFR(17) TFR(29) TFR(16) TFR(24)
    x0 += k1; x1 += k2 + 4u;     TFR(13) TFR(15) TFR(26) TFR(6)
    x0 += k2; x1 += k0 + 5u;
#undef TFR
    o0 = x0; o1 = x1;
}

static unsigned int h_rotl(unsigned int v, int r){ return (v<<r)|(v>>(32-r)); }
static void tf_host(unsigned int k0, unsigned int k1, unsigned int x0, unsigned int x1,
                    unsigned int& o0, unsigned int& o1) {
    unsigned int k2 = k0 ^ k1 ^ 0x1BD11BDAu;
#define TFR(r) { x0 += x1; x1 = h_rotl(x1, r); x1 ^= x0; }
    x0 += k0; x1 += k1;          TFR(13) TFR(15) TFR(26) TFR(6)
    x0 += k1; x1 += k2 + 1u;     TFR(17) TFR(29) TFR(16) TFR(24)
    x0 += k2; x1 += k0 + 2u;     TFR(13) TFR(15) TFR(26) TFR(6)
    x0 += k0; x1 += k1 + 3u;     TFR(17) TFR(29) TFR(16) TFR(24)
    x0 += k1; x1 += k2 + 4u;     TFR(13) TFR(15) TFR(26) TFR(6)
    x0 += k2; x1 += k0 + 5u;
#undef TFR
    o0 = x0; o1 = x1;
}

// ---------------- mma helpers ----------------
__device__ __forceinline__ void mma16h(float* d,
                                       unsigned int a0, unsigned int a1,
                                       unsigned int a2, unsigned int a3,
                                       unsigned int b0, unsigned int b1) {
    asm volatile(
        "mma.sync.aligned.m16n8k16.row.col.f32.f16.f16.f32 "
        "{%0,%1,%2,%3},{%4,%5,%6,%7},{%8,%9},{%0,%1,%2,%3};\n"
        : "+f"(d[0]), "+f"(d[1]), "+f"(d[2]), "+f"(d[3])
        : "r"(a0), "r"(a1), "r"(a2), "r"(a3), "r"(b0), "r"(b1));
}
__device__ __forceinline__ unsigned int pk(unsigned int t) {
    return 0x3C003C00u | ((t & 1u) << 15) | ((t & 2u) << 30);
}
__device__ __forceinline__ unsigned int h2pack(float lo, float hi) {
    __half2 h = __floats2half2_rn(lo, hi);
    return *(unsigned int*)&h;
}

// ---------------- prep ----------------
__global__ void prep_kernel(const float* __restrict__ x,
                            const float* __restrict__ W1,
                            const float* __restrict__ b1,
                            const float* __restrict__ W2) {
    int i = blockIdx.x * 256 + threadIdx.x;
    if (i < DD * HH) {
        int d = i >> 10, j = i & 1023;
        g_W2t[i] = W2[j * DD + d];
    }
    if (i < 4 * HH) {
        const float tv[4] = {0.0f, 0.5f, 0.5f, 1.0f};
        int st = i >> 10, j = i & 1023;
        g_bias1[i] = b1[j] + tv[st] * W1[256 * HH + j];
    }
    if (i < BB) g_accd[i] = 0.0f;
    if (i < (BB * DD) / 2) {
        float2 v = *(const float2*)(x + 2 * i);
        g_xh[i] = h2pack(v.x, v.y);
    }
    if (i < 128 * HH) {
        int kp = i >> 10, n = i & 1023;
        g_W1p[i] = h2pack(W1[(size_t)(2*kp) * HH + n], W1[(size_t)(2*kp+1) * HH + n]);
    }
    if (i < 512 * DD) {
        int kp = i >> 8, n = i & 255;
        g_W2p[i] = h2pack(W2[(size_t)(2*kp) * DD + n], W2[(size_t)(2*kp+1) * DD + n]);
    }
}

// ---------------- RNG ----------------
__global__ __launch_bounds__(256) void rng_kernel(unsigned int k0, unsigned int k1,
                                                  int st) {
    unsigned int j = blockIdx.x * 256u + threadIdx.x;
    unsigned int o0, o1;
    tf_dev(k0, k1, 0u, j, o0, o1);
    unsigned int word = __ballot_sync(0xffffffffu, (o0 ^ o1) & 1u);
    if ((threadIdx.x & 31u) == 0u) g_ebits[st][j >> 5] = word;
}

// ---------------- S kernel: uint4 fused-B layout, per-stage launch -----------
// sW4[kq][n] uint4 = {W1h2[kp], W1h2[kp+4], W2h2[kp], W2h2[kp+4]},
//   kp = (kq>>2)*8 + (kq&3); row stride 66 uint4 (conflict-free phases).
// sE[PP][64][8] packed probe bits.
#define SW4_STRIDE 66
#define SW4_BYTES (64*SW4_STRIDE*16)          /* 67,584 */
#define SE_WORDS (PP*64*8)
#define SK_SMEM (SW4_BYTES + SE_WORDS*4)      /* 88,064 */

__global__ __launch_bounds__(256, 2) void s_kernel(const float* __restrict__ W1,
                                                   int st) {
    extern __shared__ unsigned int sm[];
    uint4* sW4 = (uint4*)sm;
    unsigned int* sE = sm + (SW4_BYTES / 4);

    int tid = threadIdx.x;
    int r0 = blockIdx.x * 64;
    int j0 = blockIdx.y * 64;

    // ---- build fused W tile ----
#pragma unroll 4
    for (int it = 0; it < 16; ++it) {
        int id = tid + it * 256;            // 0..4095
        int kq = id >> 6, n = id & 63;
        int kp = ((kq >> 2) << 3) + (kq & 3);
        const float* w1a = W1 + (size_t)(2*kp) * HH + j0 + n;
        const float* w1b = W1 + (size_t)(2*kp+8) * HH + j0 + n;   // kp+4 pair
        const float* w2a = g_W2t + (size_t)(2*kp) * HH + j0 + n;
        const float* w2b = g_W2t + (size_t)(2*kp+8) * HH + j0 + n;
        uint4 e;
        e.x = h2pack(w1a[0], w1a[HH]);
        e.y = h2pack(w1b[0], w1b[HH]);
        e.z = h2pack(w2a[0], w2a[HH]);
        e.w = h2pack(w2b[0], w2b[HH]);
        sW4[kq * SW4_STRIDE + n] = e;
    }
    for (int id = tid; id < SE_WORDS; id += 256) {
        int p = id / (64 * 8);
        int rem = id - p * (64 * 8);
        int rr = rem >> 3, w = rem & 7;
        sE[id] = g_ebits[st][((size_t)(p * BB + r0 + rr) << 3) + w];
    }
    __syncthreads();

    int lane = tid & 31, wid = tid >> 5;
    int wm = (wid & 3) * 16;
    int wn = (wid >> 2) * 32;
    int grp = lane >> 2, qd = lane & 3;

    float sacc[16];
#pragma unroll
    for (int i = 0; i < 16; ++i) sacc[i] = 0.0f;

    for (int pp = 0; pp < PP; pp += 2) {
        float u0[16], g0[16], u1[16], g1[16];
#pragma unroll
        for (int i = 0; i < 16; ++i) { u0[i]=0.f; g0[i]=0.f; u1[i]=0.f; g1[i]=0.f; }
        const unsigned int* e0a = &sE[(pp * 64 + wm + grp) * 8];
        const unsigned int* e0b = e0a + 64;
        const unsigned int* e1a = &sE[((pp + 1) * 64 + wm + grp) * 8];
        const unsigned int* e1b = e1a + 64;
#pragma unroll 4
        for (int ks = 0; ks < 256; ks += 16) {
            int wi = ks >> 5;
            int sh = (ks & 31) + 2 * qd;
            unsigned int t00 = ~(e0a[wi] >> sh);
            unsigned int t01 = ~(e0b[wi] >> sh);
            unsigned int t10 = ~(e1a[wi] >> sh);
            unsigned int t11 = ~(e1b[wi] >> sh);
            unsigned int A00 = pk(t00), A01 = pk(t01);
            unsigned int A02 = pk(t00 >> 8), A03 = pk(t01 >> 8);
            unsigned int A10 = pk(t10), A11 = pk(t11);
            unsigned int A12 = pk(t10 >> 8), A13 = pk(t11 >> 8);
            const uint4* bp = sW4 + (((ks >> 4) << 2) + qd) * SW4_STRIDE + wn + grp;
#pragma unroll
            for (int t = 0; t < 4; ++t) {
                uint4 b = bp[t * 8];
                mma16h(&u0[t*4], A00,A01,A02,A03, b.x, b.y);
                mma16h(&u1[t*4], A10,A11,A12,A13, b.x, b.y);
                mma16h(&g0[t*4], A00,A01,A02,A03, b.z, b.w);
                mma16h(&g1[t*4], A10,A11,A12,A13, b.z, b.w);
            }
        }
#pragma unroll
        for (int i = 0; i < 16; ++i) sacc[i] += u0[i]*g0[i] + u1[i]*g1[i];
    }

    const float inv = 1.0f / (float)PP;
    int rg = r0 + wm + grp;
#pragma unroll
    for (int t = 0; t < 4; ++t) {
        int col = j0 + wn + t * 8 + qd * 2;
        float2 v0 = make_float2(sacc[t*4+0]*inv, sacc[t*4+1]*inv);
        float2 v1 = make_float2(sacc[t*4+2]*inv, sacc[t*4+3]*inv);
        *(float2*)&g_S[st][rg * HH + col]       = v0;
        *(float2*)&g_S[st][(rg + 8) * HH + col] = v1;
    }
}

// ---------------- fused main-chain GEMM, fp16 ----------------
#define GEMM_SMEM ((2*(128*20 + 16*136)) * 4 + 128 * 4)

template<int MODE>
__global__ __launch_bounds__(256) void gemm_kernel(
    const uint32_t* __restrict__ Ah, const uint32_t* __restrict__ Bp,
    const float* __restrict__ bias, uint32_t* __restrict__ Hout,
    const float* __restrict__ S, float* __restrict__ accd,
    const float* __restrict__ x, float* __restrict__ accz, uint32_t* __restrict__ z,
    int N, int K, int st, float wq, float cq)
{
    extern __shared__ unsigned int dsm[];
    unsigned int* sA = dsm;
    unsigned int* sB = dsm + 2 * 128 * 20;
    float* rowsum = (float*)(dsm + 2*128*20 + 2*16*136);

    int tid = threadIdx.x, lane = tid & 31, wid = tid >> 5;
    int m0 = blockIdx.x * 128, n0 = blockIdx.y * 128;
    int wm = (wid & 1) * 64, wn = (wid >> 1) * 32;
    int grp = lane >> 2, qd = lane & 3;
    int K2 = K >> 1;

    if (MODE == 1 && tid < 128) rowsum[tid] = 0.0f;

    float acc[4][4][4];
#pragma unroll
    for (int a = 0; a < 4; ++a)
#pragma unroll
        for (int b = 0; b < 4; ++b)
#pragma unroll
            for (int cc = 0; cc < 4; ++cc) acc[a][b][cc] = 0.0f;

    uint4 va[2], vb[2];
    int nch = K / 32;

#define LOADG(KC2) { \
    _Pragma("unroll") \
    for (int it = 0; it < 2; ++it) { \
        int f = tid + it * 256; \
        int ra = f >> 2, ca = f & 3; \
        va[it] = *(const uint4*)(Ah + (size_t)(m0 + ra) * K2 + (KC2) + ca * 4); \
        int rb = f >> 5, cb = f & 31; \
        vb[it] = *(const uint4*)(Bp + (size_t)((KC2) + rb) * N + n0 + cb * 4); \
    } }

#define STOREB(BUF) { \
    unsigned int* dA = sA + (BUF) * (128 * 20); \
    unsigned int* dB = sB + (BUF) * (16 * 136); \
    _Pragma("unroll") \
    for (int it = 0; it < 2; ++it) { \
        int f = tid + it * 256; \
        int ra = f >> 2, ca = f & 3; \
        *(uint4*)&dA[ra * 20 + ca * 4] = va[it]; \
        int rb = f >> 5, cb = f & 31; \
        *(uint4*)&dB[rb * 136 + cb * 4] = vb[it]; \
    } }

    LOADG(0); STOREB(0); __syncthreads();

    for (int ch = 0; ch < nch; ++ch) {
        if (ch + 1 < nch) LOADG((ch + 1) * 16);
        const unsigned int* bA = sA + (ch & 1) * (128 * 20);
        const unsigned int* bB = sB + (ch & 1) * (16 * 136);
#pragma unroll
        for (int kq = 0; kq < 2; ++kq) {
            int kb = kq * 8;
            unsigned int ar[4][4];
#pragma unroll
            for (int mi = 0; mi < 4; ++mi) {
                int r = wm + mi * 16 + grp;
                ar[mi][0] = bA[r * 20 + kb + qd];
                ar[mi][1] = bA[(r + 8) * 20 + kb + qd];
                ar[mi][2] = bA[r * 20 + kb + qd + 4];
                ar[mi][3] = bA[(r + 8) * 20 + kb + qd + 4];
            }
            unsigned int br[4][2];
#pragma unroll
            for (int ni = 0; ni < 4; ++ni) {
                int n = wn + ni * 8 + grp;
                br[ni][0] = bB[(kb + qd) * 136 + n];
                br[ni][1] = bB[(kb + qd + 4) * 136 + n];
            }
#pragma unroll
            for (int mi = 0; mi < 4; ++mi)
#pragma unroll
                for (int ni = 0; ni < 4; ++ni)
                    mma16h(acc[mi][ni], ar[mi][0],ar[mi][1],ar[mi][2],ar[mi][3],
                           br[ni][0], br[ni][1]);
        }
        if (ch + 1 < nch) STOREB((ch + 1) & 1);
        __syncthreads();
    }
#undef LOADG
#undef STOREB

    if (MODE == 1) {
#pragma unroll
        for (int mi = 0; mi < 4; ++mi)
#pragma unroll
            for (int half = 0; half < 2; ++half) {
                int r = m0 + wm + mi * 16 + grp + half * 8;
                float ds = 0.0f;
#pragma unroll
                for (int ni = 0; ni < 4; ++ni) {
                    int col = n0 + wn + ni * 8 + qd * 2;
                    float v0 = tanhf(acc[mi][ni][half*2+0] + bias[col]);
                    float v1 = tanhf(acc[mi][ni][half*2+1] + bias[col+1]);
                    Hout[((size_t)r * HH + col) >> 1] = h2pack(v0, v1);
                    float2 sv = *(const float2*)&S[(size_t)r * HH + col];
                    ds = fmaf(1.0f - v0*v0, sv.x, ds);
                    ds = fmaf(1.0f - v1*v1, sv.y, ds);
                }
                ds += __shfl_xor_sync(0xffffffffu, ds, 1);
                ds += __shfl_xor_sync(0xffffffffu, ds, 2);
                if (qd == 0) atomicAdd(&rowsum[wm + mi*16 + grp + half*8], ds);
            }
        __syncthreads();
        if (tid < 128) atomicAdd(&accd[m0 + tid], wq * rowsum[tid]);
    } else {
#pragma unroll
        for (int mi = 0; mi < 4; ++mi)
#pragma unroll
            for (int half = 0; half < 2; ++half) {
                int r = m0 + wm + mi * 16 + grp + half * 8;
#pragma unroll
                for (int ni = 0; ni < 4; ++ni) {
                    int col = n0 + wn + ni * 8 + qd * 2;
                    float f0 = acc[mi][ni][half*2+0] + bias[col];
                    float f1 = acc[mi][ni][half*2+1] + bias[col+1];
                    size_t idx = (size_t)r * DD + col;
                    float2 az;
                    if (st == 0) az = make_float2(0.f, 0.f);
                    else az = *(float2*)&accz[idx];
                    az.x += wq * f0; az.y += wq * f1;
                    *(float2*)&accz[idx] = az;
                    if (st < 3) {
                        float2 xx = *(const float2*)&x[idx];
                        z[idx >> 1] = h2pack(xx.x + cq*f0, xx.y + cq*f1);
                    }
                }
            }
    }
}

// ---------------- final ----------------
__global__ __launch_bounds__(256) void final_kernel(const float* __restrict__ x,
                                                    float* __restrict__ out) {
    int i = blockIdx.x * 256 + threadIdx.x;
    const int half = BB * 257;
    if (i >= 2 * half) return;
    if (i < half) {
        int r = i / 257, d = i - r * 257;
        out[i] = (d < 256) ? x[r * DD + d] : 0.0f;
    } else {
        int j = i - half;
        int r = j / 257, d = j - r * 257;
        out[i] = (d < 256) ? x[r * DD + d] + g_accz[r * DD + d] * (1.0f / 6.0f)
                           : -g_accd[r] * (1.0f / 6.0f);
    }
}

// ---------------- launch ----------------
extern "C" void kernel_launch(void* const* d_in, const int* in_sizes, int n_in,
                              void* d_out, int out_size) {
    const float* x  = (const float*)d_in[0];
    const float* W1 = (const float*)d_in[1];
    const float* b1 = (const float*)d_in[2];
    const float* W2 = (const float*)d_in[3];
    const float* b2 = (const float*)d_in[4];
    float* out = (float*)d_out;
    (void)in_sizes; (void)n_in; (void)out_size;

    unsigned int kk[4][2];
    for (unsigned int st = 0; st < 4; ++st) {
        unsigned int f0, f1;
        tf_host(0u, 42u, 0u, st, f0, f1);
        tf_host(f0, f1, 0u, 1u, kk[st][0], kk[st][1]);
    }

    float *gbias, *gS, *gaccd, *gaccz;
    uint32_t *gxh, *gzh, *ghh, *gW1p, *gW2p;
    cudaGetSymbolAddress((void**)&gbias, g_bias1);
    cudaGetSymbolAddress((void**)&gS,    g_S);
    cudaGetSymbolAddress((void**)&gaccd, g_accd);
    cudaGetSymbolAddress((void**)&gaccz, g_accz);
    cudaGetSymbolAddress((void**)&gxh,   g_xh);
    cudaGetSymbolAddress((void**)&gzh,   g_zh);
    cudaGetSymbolAddress((void**)&ghh,   g_hh);
    cudaGetSymbolAddress((void**)&gW1p,  g_W1p);
    cudaGetSymbolAddress((void**)&gW2p,  g_W2p);

    cudaFuncSetAttribute(s_kernel, cudaFuncAttributeMaxDynamicSharedMemorySize, SK_SMEM);
    cudaFuncSetAttribute(gemm_kernel<0>, cudaFuncAttributeMaxDynamicSharedMemorySize, GEMM_SMEM);
    cudaFuncSetAttribute(gemm_kernel<1>, cudaFuncAttributeMaxDynamicSharedMemorySize, GEMM_SMEM);

    prep_kernel<<<(BB*DD/2 + 255) / 256, 256>>>(x, W1, b1, W2);
    for (int st = 0; st < 4; ++st)
        rng_kernel<<<NE / 256, 256>>>(kk[st][0], kk[st][1], st);
    for (int st = 0; st < 4; ++st)
        s_kernel<<<dim3(BB / 64, HH / 64), 256, SK_SMEM>>>(W1, st);

    const float wst[4] = {1.0f, 2.0f, 2.0f, 1.0f};
    const float cst[4] = {0.5f, 0.5f, 1.0f, 0.0f};
    for (int st = 0; st < 4; ++st) {
        const uint32_t* Ain = (st == 0) ? gxh : gzh;
        gemm_kernel<1><<<dim3(BB/128, HH/128), 256, GEMM_SMEM>>>(
            Ain, gW1p, gbias + st*HH, ghh,
            gS + (size_t)st * BB * HH, gaccd,
            nullptr, nullptr, nullptr,
            HH, DD, st, wst[st], cst[st]);
        gemm_kernel<0><<<dim3(BB/128, DD/128), 256, GEMM_SMEM>>>(
            ghh, gW2p, b2, nullptr,
            nullptr, nullptr,
            x, gaccz, gzh,
            DD, HH, st, wst[st], cst[st]);
    }
    final_kernel<<<(2*BB*257 + 255)/256, 256>>>(x, out);
}

// round 10
// speedup vs baseline: 1.0026x; 1.0026x over previous
#include <cuda_runtime.h>
#include <cuda_fp16.h>
#include <cstdint>

#define BB 4096
#define DD 256
#define HH 1024
#define PP 10
#define NE (PP*BB*DD)
#define NWORDS (NE/32)

// ---------------- device scratch ----------------
__device__ uint32_t g_ebits[4][NWORDS];
__device__ float    g_S[4][BB*HH];
__device__ float    g_W2t[DD*HH];
__device__ float    g_bias1[4*HH];
__device__ uint32_t g_hh[BB*HH/2];      // h as half2
__device__ uint32_t g_zh[BB*DD/2];      // z as half2
__device__ uint32_t g_xh[BB*DD/2];      // x as half2
__device__ uint32_t g_W1p[128*HH];      // W1 k-paired half2
__device__ uint32_t g_W2p[512*DD];      // W2 k-paired half2
__device__ float    g_accz[BB*DD];
__device__ float    g_accd[BB];

// ---------------- Threefry-2x32 ----------------
__device__ __forceinline__ void tf_dev(unsigned int k0, unsigned int k1,
                                       unsigned int x0, unsigned int x1,
                                       unsigned int& o0, unsigned int& o1) {
    unsigned int k2 = k0 ^ k1 ^ 0x1BD11BDAu;
#define TFR(r) { x0 += x1; x1 = __funnelshift_l(x1, x1, r); x1 ^= x0; }
    x0 += k0; x1 += k1;          TFR(13) TFR(15) TFR(26) TFR(6)
    x0 += k1; x1 += k2 + 1u;     TFR(17) TFR(29) TFR(16) TFR(24)
    x0 += k2; x1 += k0 + 2u;     TFR(13) TFR(15) TFR(26) TFR(6)
    x0 += k0; x1 += k1 + 3u;     TFR(17) TFR(29) TFR(16) TFR(24)
    x0 += k1; x1 += k2 + 4u;     TFR(13) TFR(15) TFR(26) TFR(6)
    x0 += k2; x1 += k0 + 5u;
#undef TFR
    o0 = x0; o1 = x1;
}

static unsigned int h_rotl(unsigned int v, int r){ return (v<<r)|(v>>(32-r)); }
static void tf_host(unsigned int k0, unsigned int k1, unsigned int x0, unsigned int x1,
                    unsigned int& o0, unsigned int& o1) {
    unsigned int k2 = k0 ^ k1 ^ 0x1BD11BDAu;
#define TFR(r) { x0 += x1; x1 = h_rotl(x1, r); x1 ^= x0; }
    x0 += k0; x1 += k1;          TFR(13) TFR(15) TFR(26) TFR(6)
    x0 += k1; x1 += k2 + 1u;     TFR(17) TFR(29) TFR(16) TFR(24)
    x0 += k2; x1 += k0 + 2u;     TFR(13) TFR(15) TFR(26) TFR(6)
    x0 += k0; x1 += k1 + 3u;     TFR(17) TFR(29) TFR(16) TFR(24)
    x0 += k1; x1 += k2 + 4u;     TFR(13) TFR(15) TFR(26) TFR(6)
    x0 += k2; x1 += k0 + 5u;
#undef TFR
    o0 = x0; o1 = x1;
}

// ---------------- mma helpers ----------------
__device__ __forceinline__ void mma16h(float* d,
                                       unsigned int a0, unsigned int a1,
                                       unsigned int a2, unsigned int a3,
                                       unsigned int b0, unsigned int b1) {
    asm volatile(
        "mma.sync.aligned.m16n8k16.row.col.f32.f16.f16.f32 "
        "{%0,%1,%2,%3},{%4,%5,%6,%7},{%8,%9},{%0,%1,%2,%3};\n"
        : "+f"(d[0]), "+f"(d[1]), "+f"(d[2]), "+f"(d[3])
        : "r"(a0), "r"(a1), "r"(a2), "r"(a3), "r"(b0), "r"(b1));
}
__device__ __forceinline__ unsigned int pk(unsigned int t) {
    return 0x3C003C00u | ((t & 1u) << 15) | ((t & 2u) << 30);
}
__device__ __forceinline__ unsigned int h2pack(float lo, float hi) {
    __half2 h = __floats2half2_rn(lo, hi);
    return *(unsigned int*)&h;
}

// ---------------- prep ----------------
__global__ void prep_kernel(const float* __restrict__ x,
                            const float* __restrict__ W1,
                            const float* __restrict__ b1,
                            const float* __restrict__ W2) {
    int i = blockIdx.x * 256 + threadIdx.x;
    if (i < DD * HH) {
        int d = i >> 10, j = i & 1023;
        g_W2t[i] = W2[j * DD + d];
    }
    if (i < 4 * HH) {
        const float tv[4] = {0.0f, 0.5f, 0.5f, 1.0f};
        int st = i >> 10, j = i & 1023;
        g_bias1[i] = b1[j] + tv[st] * W1[256 * HH + j];
    }
    if (i < BB) g_accd[i] = 0.0f;
    if (i < (BB * DD) / 2) {
        float2 v = *(const float2*)(x + 2 * i);
        g_xh[i] = h2pack(v.x, v.y);
    }
    if (i < 128 * HH) {
        int kp = i >> 10, n = i & 1023;
        g_W1p[i] = h2pack(W1[(size_t)(2*kp) * HH + n], W1[(size_t)(2*kp+1) * HH + n]);
    }
    if (i < 512 * DD) {
        int kp = i >> 8, n = i & 255;
        g_W2p[i] = h2pack(W2[(size_t)(2*kp) * DD + n], W2[(size_t)(2*kp+1) * DD + n]);
    }
}

// ---------------- RNG ----------------
__global__ __launch_bounds__(256) void rng_kernel(unsigned int k0, unsigned int k1,
                                                  int st) {
    unsigned int j = blockIdx.x * 256u + threadIdx.x;
    unsigned int o0, o1;
    tf_dev(k0, k1, 0u, j, o0, o1);
    unsigned int word = __ballot_sync(0xffffffffu, (o0 ^ o1) & 1u);
    if ((threadIdx.x & 31u) == 0u) g_ebits[st][j >> 5] = word;
}

// ---------------- S kernel: uint4 fused-B layout, per-stage launch -----------
// sW4[kq][n] uint4 = {W1h2[kp], W1h2[kp+4], W2h2[kp], W2h2[kp+4]},
//   kp = (kq>>2)*8 + (kq&3); row stride 66 uint4 (conflict-free phases).
// sE[PP][64][8] packed probe bits.
#define SW4_STRIDE 66
#define SW4_BYTES (64*SW4_STRIDE*16)          /* 67,584 */
#define SE_WORDS (PP*64*8)
#define SK_SMEM (SW4_BYTES + SE_WORDS*4)      /* 88,064 */

__global__ __launch_bounds__(256, 2) void s_kernel(const float* __restrict__ W1,
                                                   int st) {
    extern __shared__ unsigned int sm[];
    uint4* sW4 = (uint4*)sm;
    unsigned int* sE = sm + (SW4_BYTES / 4);

    int tid = threadIdx.x;
    int r0 = blockIdx.x * 64;
    int j0 = blockIdx.y * 64;

    // ---- build fused W tile ----
#pragma unroll 4
    for (int it = 0; it < 16; ++it) {
        int id = tid + it * 256;            // 0..4095
        int kq = id >> 6, n = id & 63;
        int kp = ((kq >> 2) << 3) + (kq & 3);
        const float* w1a = W1 + (size_t)(2*kp) * HH + j0 + n;
        const float* w1b = W1 + (size_t)(2*kp+8) * HH + j0 + n;   // kp+4 pair
        const float* w2a = g_W2t + (size_t)(2*kp) * HH + j0 + n;
        const float* w2b = g_W2t + (size_t)(2*kp+8) * HH + j0 + n;
        uint4 e;
        e.x = h2pack(w1a[0], w1a[HH]);
        e.y = h2pack(w1b[0], w1b[HH]);
        e.z = h2pack(w2a[0], w2a[HH]);
        e.w = h2pack(w2b[0], w2b[HH]);
        sW4[kq * SW4_STRIDE + n] = e;
    }
    for (int id = tid; id < SE_WORDS; id += 256) {
        int p = id / (64 * 8);
        int rem = id - p * (64 * 8);
        int rr = rem >> 3, w = rem & 7;
        sE[id] = g_ebits[st][((size_t)(p * BB + r0 + rr) << 3) + w];
    }
    __syncthreads();

    int lane = tid & 31, wid = tid >> 5;
    int wm = (wid & 3) * 16;
    int wn = (wid >> 2) * 32;
    int grp = lane >> 2, qd = lane & 3;

    float sacc[16];
#pragma unroll
    for (int i = 0; i < 16; ++i) sacc[i] = 0.0f;

    for (int pp = 0; pp < PP; pp += 2) {
        float u0[16], g0[16], u1[16], g1[16];
#pragma unroll
        for (int i = 0; i < 16; ++i) { u0[i]=0.f; g0[i]=0.f; u1[i]=0.f; g1[i]=0.f; }
        const unsigned int* e0a = &sE[(pp * 64 + wm + grp) * 8];
        const unsigned int* e0b = e0a + 64;
        const unsigned int* e1a = &sE[((pp + 1) * 64 + wm + grp) * 8];
        const unsigned int* e1b = e1a + 64;
#pragma unroll 4
        for (int ks = 0; ks < 256; ks += 16) {
            int wi = ks >> 5;
            int sh = (ks & 31) + 2 * qd;
            unsigned int t00 = ~(e0a[wi] >> sh);
            unsigned int t01 = ~(e0b[wi] >> sh);
            unsigned int t10 = ~(e1a[wi] >> sh);
            unsigned int t11 = ~(e1b[wi] >> sh);
            unsigned int A00 = pk(t00), A01 = pk(t01);
            unsigned int A02 = pk(t00 >> 8), A03 = pk(t01 >> 8);
            unsigned int A10 = pk(t10), A11 = pk(t11);
            unsigned int A12 = pk(t10 >> 8), A13 = pk(t11 >> 8);
            const uint4* bp = sW4 + (((ks >> 4) << 2) + qd) * SW4_STRIDE + wn + grp;
#pragma unroll
            for (int t = 0; t < 4; ++t) {
                uint4 b = bp[t * 8];
                mma16h(&u0[t*4], A00,A01,A02,A03, b.x, b.y);
                mma16h(&u1[t*4], A10,A11,A12,A13, b.x, b.y);
                mma16h(&g0[t*4], A00,A01,A02,A03, b.z, b.w);
                mma16h(&g1[t*4], A10,A11,A12,A13, b.z, b.w);
            }
        }
#pragma unroll
        for (int i = 0; i < 16; ++i) sacc[i] += u0[i]*g0[i] + u1[i]*g1[i];
    }

    const float inv = 1.0f / (float)PP;
    int rg = r0 + wm + grp;
#pragma unroll
    for (int t = 0; t < 4; ++t) {
        int col = j0 + wn + t * 8 + qd * 2;
        float2 v0 = make_float2(sacc[t*4+0]*inv, sacc[t*4+1]*inv);
        float2 v1 = make_float2(sacc[t*4+2]*inv, sacc[t*4+3]*inv);
        *(float2*)&g_S[st][rg * HH + col]       = v0;
        *(float2*)&g_S[st][(rg + 8) * HH + col] = v1;
    }
}

// ---------------- fused main-chain GEMM, fp16 ----------------
#define GEMM_SMEM ((2*(128*20 + 16*136)) * 4 + 128 * 4)

template<int MODE>
__global__ __launch_bounds__(256) void gemm_kernel(
    const uint32_t* __restrict__ Ah, const uint32_t* __restrict__ Bp,
    const float* __restrict__ bias, uint32_t* __restrict__ Hout,
    const float* __restrict__ S, float* __restrict__ accd,
    const float* __restrict__ x, float* __restrict__ accz, uint32_t* __restrict__ z,
    int N, int K, int st, float wq, float cq)
{
    extern __shared__ unsigned int dsm[];
    unsigned int* sA = dsm;
    unsigned int* sB = dsm + 2 * 128 * 20;
    float* rowsum = (float*)(dsm + 2*128*20 + 2*16*136);

    int tid = threadIdx.x, lane = tid & 31, wid = tid >> 5;
    int m0 = blockIdx.x * 128, n0 = blockIdx.y * 128;
    int wm = (wid & 1) * 64, wn = (wid >> 1) * 32;
    int grp = lane >> 2, qd = lane & 3;
    int K2 = K >> 1;

    if (MODE == 1 && tid < 128) rowsum[tid] = 0.0f;

    float acc[4][4][4];
#pragma unroll
    for (int a = 0; a < 4; ++a)
#pragma unroll
        for (int b = 0; b < 4; ++b)
#pragma unroll
            for (int cc = 0; cc < 4; ++cc) acc[a][b][cc] = 0.0f;

    uint4 va[2], vb[2];
    int nch = K / 32;

#define LOADG(KC2) { \
    _Pragma("unroll") \
    for (int it = 0; it < 2; ++it) { \
        int f = tid + it * 256; \
        int ra = f >> 2, ca = f & 3; \
        va[it] = *(const uint4*)(Ah + (size_t)(m0 + ra) * K2 + (KC2) + ca * 4); \
        int rb = f >> 5, cb = f & 31; \
        vb[it] = *(const uint4*)(Bp + (size_t)((KC2) + rb) * N + n0 + cb * 4); \
    } }

#define STOREB(BUF) { \
    unsigned int* dA = sA + (BUF) * (128 * 20); \
    unsigned int* dB = sB + (BUF) * (16 * 136); \
    _Pragma("unroll") \
    for (int it = 0; it < 2; ++it) { \
        int f = tid + it * 256; \
        int ra = f >> 2, ca = f & 3; \
        *(uint4*)&dA[ra * 20 + ca * 4] = va[it]; \
        int rb = f >> 5, cb = f & 31; \
        *(uint4*)&dB[rb * 136 + cb * 4] = vb[it]; \
    } }

    LOADG(0); STOREB(0); __syncthreads();

    for (int ch = 0; ch < nch; ++ch) {
        if (ch + 1 < nch) LOADG((ch + 1) * 16);
        const unsigned int* bA = sA + (ch & 1) * (128 * 20);
        const unsigned int* bB = sB + (ch & 1) * (16 * 136);
#pragma unroll
        for (int kq = 0; kq < 2; ++kq) {
            int kb = kq * 8;
            unsigned int ar[4][4];
#pragma unroll
            for (int mi = 0; mi < 4; ++mi) {
                int r = wm + mi * 16 + grp;
                ar[mi][0] = bA[r * 20 + kb + qd];
                ar[mi][1] = bA[(r + 8) * 20 + kb + qd];
                ar[mi][2] = bA[r * 20 + kb + qd + 4];
                ar[mi][3] = bA[(r + 8) * 20 + kb + qd + 4];
            }
            unsigned int br[4][2];
#pragma unroll
            for (int ni = 0; ni < 4; ++ni) {
                int n = wn + ni * 8 + grp;
                br[ni][0] = bB[(kb + qd) * 136 + n];
                br[ni][1] = bB[(kb + qd + 4) * 136 + n];
            }
#pragma unroll
            for (int mi = 0; mi < 4; ++mi)
#pragma unroll
                for (int ni = 0; ni < 4; ++ni)
                    mma16h(acc[mi][ni], ar[mi][0],ar[mi][1],ar[mi][2],ar[mi][3],
                           br[ni][0], br[ni][1]);
        }
        if (ch + 1 < nch) STOREB((ch + 1) & 1);
        __syncthreads();
    }
#undef LOADG
#undef STOREB

    if (MODE == 1) {
#pragma unroll
        for (int mi = 0; mi < 4; ++mi)
#pragma unroll
            for (int half = 0; half < 2; ++half) {
                int r = m0 + wm + mi * 16 + grp + half * 8;
                float ds = 0.0f;
#pragma unroll
                for (int ni = 0; ni < 4; ++ni) {
                    int col = n0 + wn + ni * 8 + qd * 2;
                    float v0 = tanhf(acc[mi][ni][half*2+0] + bias[col]);
                    float v1 = tanhf(acc[mi][ni][half*2+1] + bias[col+1]);
                    Hout[((size_t)r * HH + col) >> 1] = h2pack(v0, v1);
                    float2 sv = *(const float2*)&S[(size_t)r * HH + col];
                    ds = fmaf(1.0f - v0*v0, sv.x, ds);
                    ds = fmaf(1.0f - v1*v1, sv.y, ds);
                }
                ds += __shfl_xor_sync(0xffffffffu, ds, 1);
                ds += __shfl_xor_sync(0xffffffffu, ds, 2);
                if (qd == 0) atomicAdd(&rowsum[wm + mi*16 + grp + half*8], ds);
            }
        __syncthreads();
        if (tid < 128) atomicAdd(&accd[m0 + tid], wq * rowsum[tid]);
    } else {
#pragma unroll
        for (int mi = 0; mi < 4; ++mi)
#pragma unroll
            for (int half = 0; half < 2; ++half) {
                int r = m0 + wm + mi * 16 + grp + half * 8;
#pragma unroll
                for (int ni = 0; ni < 4; ++ni) {
                    int col = n0 + wn + ni * 8 + qd * 2;
                    float f0 = acc[mi][ni][half*2+0] + bias[col];
                    float f1 = acc[mi][ni][half*2+1] + bias[col+1];
                    size_t idx = (size_t)r * DD + col;
                    float2 az;
                    if (st == 0) az = make_float2(0.f, 0.f);
                    else az = *(float2*)&accz[idx];
                    az.x += wq * f0; az.y += wq * f1;
                    *(float2*)&accz[idx] = az;
                    if (st < 3) {
                        float2 xx = *(const float2*)&x[idx];
                        z[idx >> 1] = h2pack(xx.x + cq*f0, xx.y + cq*f1);
                    }
                }
            }
    }
}

// ---------------- final ----------------
__global__ __launch_bounds__(256) void final_kernel(const float* __restrict__ x,
                                                    float* __restrict__ out) {
    int i = blockIdx.x * 256 + threadIdx.x;
    const int half = BB * 257;
    if (i >= 2 * half) return;
    if (i < half) {
        int r = i / 257, d = i - r * 257;
        out[i] = (d < 256) ? x[r * DD + d] : 0.0f;
    } else {
        int j = i - half;
        int r = j / 257, d = j - r * 257;
        out[i] = (d < 256) ? x[r * DD + d] + g_accz[r * DD + d] * (1.0f / 6.0f)
                           : -g_accd[r] * (1.0f / 6.0f);
    }
}

// ---------------- launch ----------------
extern "C" void kernel_launch(void* const* d_in, const int* in_sizes, int n_in,
                              void* d_out, int out_size) {
    const float* x  = (const float*)d_in[0];
    const float* W1 = (const float*)d_in[1];
    const float* b1 = (const float*)d_in[2];
    const float* W2 = (const float*)d_in[3];
    const float* b2 = (const float*)d_in[4];
    float* out = (float*)d_out;
    (void)in_sizes; (void)n_in; (void)out_size;

    unsigned int kk[4][2];
    for (unsigned int st = 0; st < 4; ++st) {
        unsigned int f0, f1;
        tf_host(0u, 42u, 0u, st, f0, f1);
        tf_host(f0, f1, 0u, 1u, kk[st][0], kk[st][1]);
    }

    float *gbias, *gS, *gaccd, *gaccz;
    uint32_t *gxh, *gzh, *ghh, *gW1p, *gW2p;
    cudaGetSymbolAddress((void**)&gbias, g_bias1);
    cudaGetSymbolAddress((void**)&gS,    g_S);
    cudaGetSymbolAddress((void**)&gaccd, g_accd);
    cudaGetSymbolAddress((void**)&gaccz, g_accz);
    cudaGetSymbolAddress((void**)&gxh,   g_xh);
    cudaGetSymbolAddress((void**)&gzh,   g_zh);
    cudaGetSymbolAddress((void**)&ghh,   g_hh);
    cudaGetSymbolAddress((void**)&gW1p,  g_W1p);
    cudaGetSymbolAddress((void**)&gW2p,  g_W2p);

    cudaFuncSetAttribute(s_kernel, cudaFuncAttributeMaxDynamicSharedMemorySize, SK_SMEM);
    cudaFuncSetAttribute(gemm_kernel<0>, cudaFuncAttributeMaxDynamicSharedMemorySize, GEMM_SMEM);
    cudaFuncSetAttribute(gemm_kernel<1>, cudaFuncAttributeMaxDynamicSharedMemorySize, GEMM_SMEM);

    prep_kernel<<<(BB*DD/2 + 255) / 256, 256>>>(x, W1, b1, W2);
    for (int st = 0; st < 4; ++st)
        rng_kernel<<<NE / 256, 256>>>(kk[st][0], kk[st][1], st);
    for (int st = 0; st < 4; ++st)
        s_kernel<<<dim3(BB / 64, HH / 64), 256, SK_SMEM>>>(W1, st);

    const float wst[4] = {1.0f, 2.0f, 2.0f, 1.0f};
    const float cst[4] = {0.5f, 0.5f, 1.0f, 0.0f};
    for (int st = 0; st < 4; ++st) {
        const uint32_t* Ain = (st == 0) ? gxh : gzh;
        gemm_kernel<1><<<dim3(BB/128, HH/128), 256, GEMM_SMEM>>>(
            Ain, gW1p, gbias + st*HH, ghh,
            gS + (size_t)st * BB * HH, gaccd,
            nullptr, nullptr, nullptr,
            HH, DD, st, wst[st], cst[st]);
        gemm_kernel<0><<<dim3(BB/128, DD/128), 256, GEMM_SMEM>>>(
            ghh, gW2p, b2, nullptr,
            nullptr, nullptr,
            x, gaccz, gzh,
            DD, HH, st, wst[st], cst[st]);
    }
    final_kernel<<<(2*BB*257 + 255)/256, 256>>>(x, out);
}

// round 13
// speedup vs baseline: 1.0414x; 1.0387x over previous
#include <cuda_runtime.h>
#include <cuda_fp16.h>
#include <cstdint>

#define BB 4096
#define DD 256
#define HH 1024
#define PP 10
#define NE (PP*BB*DD)
#define NWORDS (NE/32)

// ---------------- device scratch ----------------
__device__ uint32_t g_ebits[4][NWORDS];
__device__ float    g_S[4][BB*HH];
__device__ float    g_W2t[DD*HH];
__device__ float    g_bias1[4*HH];
__device__ uint32_t g_hh[BB*HH/2];
__device__ uint32_t g_zh[BB*DD/2];
__device__ uint32_t g_xh[BB*DD/2];
__device__ uint32_t g_W1p[128*HH];
__device__ uint32_t g_W2p[512*DD];
__device__ float    g_accz[BB*DD];
__device__ float    g_accd[BB];

// ---------------- Threefry-2x32 ----------------
__device__ __forceinline__ void tf_dev(unsigned int k0, unsigned int k1,
                                       unsigned int x0, unsigned int x1,
                                       unsigned int& o0, unsigned int& o1) {
    unsigned int k2 = k0 ^ k1 ^ 0x1BD11BDAu;
#define TFR(r) { x0 += x1; x1 = __funnelshift_l(x1, x1, r); x1 ^= x0; }
    x0 += k0; x1 += k1;          TFR(13) TFR(15) TFR(26) TFR(6)
    x0 += k1; x1 += k2 + 1u;     TFR(17) TFR(29) TFR(16) TFR(24)
    x0 += k2; x1 += k0 + 2u;     TFR(13) TFR(15) TFR(26) TFR(6)
    x0 += k0; x1 += k1 + 3u;     TFR(17) TFR(29) TFR(16) TFR(24)
    x0 += k1; x1 += k2 + 4u;     TFR(13) TFR(15) TFR(26) TFR(6)
    x0 += k2; x1 += k0 + 5u;
#undef TFR
    o0 = x0; o1 = x1;
}

static unsigned int h_rotl(unsigned int v, int r){ return (v<<r)|(v>>(32-r)); }
static void tf_host(unsigned int k0, unsigned int k1, unsigned int x0, unsigned int x1,
                    unsigned int& o0, unsigned int& o1) {
    unsigned int k2 = k0 ^ k1 ^ 0x1BD11BDAu;
#define TFR(r) { x0 += x1; x1 = h_rotl(x1, r); x1 ^= x0; }
    x0 += k0; x1 += k1;          TFR(13) TFR(15) TFR(26) TFR(6)
    x0 += k1; x1 += k2 + 1u;     TFR(17) TFR(29) TFR(16) TFR(24)
    x0 += k2; x1 += k0 + 2u;     TFR(13) TFR(15) TFR(26) TFR(6)
    x0 += k0; x1 += k1 + 3u;     TFR(17) TFR(29) TFR(16) TFR(24)
    x0 += k1; x1 += k2 + 4u;     TFR(13) TFR(15) TFR(26) TFR(6)
    x0 += k2; x1 += k0 + 5u;
#undef TFR
    o0 = x0; o1 = x1;
}

// ---------------- mma helpers ----------------
__device__ __forceinline__ void mma16h(float* d,
                                       unsigned int a0, unsigned int a1,
                                       unsigned int a2, unsigned int a3,
                                       unsigned int b0, unsigned int b1) {
    asm volatile(
        "mma.sync.aligned.m16n8k16.row.col.f32.f16.f16.f32 "
        "{%0,%1,%2,%3},{%4,%5,%6,%7},{%8,%9},{%0,%1,%2,%3};\n"
        : "+f"(d[0]), "+f"(d[1]), "+f"(d[2]), "+f"(d[3])
        : "r"(a0), "r"(a1), "r"(a2), "r"(a3), "r"(b0), "r"(b1));
}
__device__ __forceinline__ unsigned int pk(unsigned int t) {
    return 0x3C003C00u | ((t & 1u) << 15) | ((t & 2u) << 30);
}
__device__ __forceinline__ unsigned int h2pack(float lo, float hi) {
    __half2 h = __floats2half2_rn(lo, hi);
    return *(unsigned int*)&h;
}

// ---------------- prep ----------------
__global__ void prep_kernel(const float* __restrict__ x,
                            const float* __restrict__ W1,
                            const float* __restrict__ b1,
                            const float* __restrict__ W2) {
    int i = blockIdx.x * 256 + threadIdx.x;
    if (i < DD * HH) {
        int d = i >> 10, j = i & 1023;
        g_W2t[i] = W2[j * DD + d];
    }
    if (i < 4 * HH) {
        const float tv[4] = {0.0f, 0.5f, 0.5f, 1.0f};
        int st = i >> 10, j = i & 1023;
        g_bias1[i] = b1[j] + tv[st] * W1[256 * HH + j];
    }
    if (i < BB) g_accd[i] = 0.0f;
    if (i < (BB * DD) / 2) {
        float2 v = *(const float2*)(x + 2 * i);
        g_xh[i] = h2pack(v.x, v.y);
    }
    if (i < 128 * HH) {
        int kp = i >> 10, n = i & 1023;
        g_W1p[i] = h2pack(W1[(size_t)(2*kp) * HH + n], W1[(size_t)(2*kp+1) * HH + n]);
    }
    if (i < 512 * DD) {
        int kp = i >> 8, n = i & 255;
        g_W2p[i] = h2pack(W2[(size_t)(2*kp) * DD + n], W2[(size_t)(2*kp+1) * DD + n]);
    }
}

// ---------------- RNG ----------------
__global__ __launch_bounds__(256) void rng_kernel(unsigned int k0, unsigned int k1,
                                                  int st) {
    unsigned int j = blockIdx.x * 256u + threadIdx.x;
    unsigned int o0, o1;
    tf_dev(k0, k1, 0u, j, o0, o1);
    unsigned int word = __ballot_sync(0xffffffffu, (o0 ^ o1) & 1u);
    if ((threadIdx.x & 31u) == 0u) g_ebits[st][j >> 5] = word;
}

// ---------------- S kernel (R8 body, per-stage launch) -----------------------
#define SK_SMEM ((2*128*72 + PP*64*8) * 4)   /* 94,208 bytes */

__global__ __launch_bounds__(256, 2) void s_kernel(const float* __restrict__ W1,
                                                   int st) {
    extern __shared__ unsigned int sm[];
    unsigned int* sW1h = sm;                  // [128][72]
    unsigned int* sW2h = sm + 128 * 72;       // [128][72]
    unsigned int* sE   = sm + 2 * 128 * 72;   // [PP][64][8]

    int tid = threadIdx.x;
    int r0 = blockIdx.x * 64;
    int j0 = blockIdx.y * 64;

#pragma unroll
    for (int it = 0; it < 8; ++it) {
        int id = tid + it * 256;
        int kp = id >> 4;
        int c4 = (id & 15) * 4;
        const float* p0 = W1 + (size_t)(2*kp)   * HH + j0 + c4;
        const float* p1 = W1 + (size_t)(2*kp+1) * HH + j0 + c4;
        float4 v0 = *(const float4*)p0, v1 = *(const float4*)p1;
        sW1h[kp*72 + c4+0] = h2pack(v0.x, v1.x);
        sW1h[kp*72 + c4+1] = h2pack(v0.y, v1.y);
        sW1h[kp*72 + c4+2] = h2pack(v0.z, v1.z);
        sW1h[kp*72 + c4+3] = h2pack(v0.w, v1.w);
        const float* q0 = g_W2t + (size_t)(2*kp)   * HH + j0 + c4;
        const float* q1 = g_W2t + (size_t)(2*kp+1) * HH + j0 + c4;
        float4 w0 = *(const float4*)q0, w1 = *(const float4*)q1;
        sW2h[kp*72 + c4+0] = h2pack(w0.x, w1.x);
        sW2h[kp*72 + c4+1] = h2pack(w0.y, w1.y);
        sW2h[kp*72 + c4+2] = h2pack(w0.z, w1.z);
        sW2h[kp*72 + c4+3] = h2pack(w0.w, w1.w);
    }
    for (int id = tid; id < PP * 64 * 8; id += 256) {
        int p = id / (64 * 8);
        int rem = id - p * (64 * 8);
        int rr = rem >> 3, w = rem & 7;
        sE[id] = g_ebits[st][((size_t)(p * BB + r0 + rr) << 3) + w];
    }
    __syncthreads();

    int lane = tid & 31, wid = tid >> 5;
    int wm = (wid & 3) * 16;
    int wn = (wid >> 2) * 32;
    int grp = lane >> 2, qd = lane & 3;

    float sacc[16];
#pragma unroll
    for (int i = 0; i < 16; ++i) sacc[i] = 0.0f;

    for (int pp = 0; pp < PP; pp += 2) {
        float u0[16], g0[16], u1[16], g1[16];
#pragma unroll
        for (int i = 0; i < 16; ++i) { u0[i]=0.f; g0[i]=0.f; u1[i]=0.f; g1[i]=0.f; }
        const unsigned int* e0a = &sE[(pp * 64 + wm + grp) * 8];
        const unsigned int* e0b = e0a + 64;
        const unsigned int* e1a = &sE[((pp + 1) * 64 + wm + grp) * 8];
        const unsigned int* e1b = e1a + 64;
#pragma unroll 4
        for (int ks = 0; ks < 256; ks += 16) {
            int wi = ks >> 5;
            int sh = (ks & 31) + 2 * qd;
            unsigned int t00 = ~(e0a[wi] >> sh);
            unsigned int t01 = ~(e0b[wi] >> sh);
            unsigned int t10 = ~(e1a[wi] >> sh);
            unsigned int t11 = ~(e1b[wi] >> sh);
            unsigned int A00 = pk(t00), A01 = pk(t01);
            unsigned int A02 = pk(t00 >> 8), A03 = pk(t01 >> 8);
            unsigned int A10 = pk(t10), A11 = pk(t11);
            unsigned int A12 = pk(t10 >> 8), A13 = pk(t11 >> 8);
            int kp0 = (ks >> 1) + qd;
#pragma unroll
            for (int t = 0; t < 4; ++t) {
                int n = wn + t * 8 + grp;
                unsigned int b10 = sW1h[kp0*72 + n], b11 = sW1h[(kp0+4)*72 + n];
                unsigned int b20 = sW2h[kp0*72 + n], b21 = sW2h[(kp0+4)*72 + n];
                mma16h(&u0[t*4], A00,A01,A02,A03, b10,b11);
                mma16h(&u1[t*4], A10,A11,A12,A13, b10,b11);
                mma16h(&g0[t*4], A00,A01,A02,A03, b20,b21);
                mma16h(&g1[t*4], A10,A11,A12,A13, b20,b21);
            }
        }
#pragma unroll
        for (int i = 0; i < 16; ++i) sacc[i] += u0[i]*g0[i] + u1[i]*g1[i];
    }

    const float inv = 1.0f / (float)PP;
    int rg = r0 + wm + grp;
#pragma unroll
    for (int t = 0; t < 4; ++t) {
        int col = j0 + wn + t * 8 + qd * 2;
        float2 v0 = make_float2(sacc[t*4+0]*inv, sacc[t*4+1]*inv);
        float2 v1 = make_float2(sacc[t*4+2]*inv, sacc[t*4+3]*inv);
        *(float2*)&g_S[st][rg * HH + col]       = v0;
        *(float2*)&g_S[st][(rg + 8) * HH + col] = v1;
    }
}

// ---------------- fused main-chain GEMM, fp16 ----------------
#define GEMM_SMEM ((2*(128*20 + 16*136)) * 4 + 128 * 4)

template<int MODE>
__global__ __launch_bounds__(256) void gemm_kernel(
    const uint32_t* __restrict__ Ah, const uint32_t* __restrict__ Bp,
    const float* __restrict__ bias, uint32_t* __restrict__ Hout,
    const float* __restrict__ S, float* __restrict__ accd,
    const float* __restrict__ x, float* __restrict__ accz, uint32_t* __restrict__ z,
    int N, int K, int st, float wq, float cq)
{
    extern __shared__ unsigned int dsm[];
    unsigned int* sA = dsm;
    unsigned int* sB = dsm + 2 * 128 * 20;
    float* rowsum = (float*)(dsm + 2*128*20 + 2*16*136);

    int tid = threadIdx.x, lane = tid & 31, wid = tid >> 5;
    int m0 = blockIdx.x * 128, n0 = blockIdx.y * 128;
    int wm = (wid & 1) * 64, wn = (wid >> 1) * 32;
    int grp = lane >> 2, qd = lane & 3;
    int K2 = K >> 1;

    if (MODE == 1 && tid < 128) rowsum[tid] = 0.0f;

    float acc[4][4][4];
#pragma unroll
    for (int a = 0; a < 4; ++a)
#pragma unroll
        for (int b = 0; b < 4; ++b)
#pragma unroll
            for (int cc = 0; cc < 4; ++cc) acc[a][b][cc] = 0.0f;

    uint4 va[2], vb[2];
    int nch = K / 32;

#define LOADG(KC2) { \
    _Pragma("unroll") \
    for (int it = 0; it < 2; ++it) { \
        int f = tid + it * 256; \
        int ra = f >> 2, ca = f & 3; \
        va[it] = *(const uint4*)(Ah + (size_t)(m0 + ra) * K2 + (KC2) + ca * 4); \
        int rb = f >> 5, cb = f & 31; \
        vb[it] = *(const uint4*)(Bp + (size_t)((KC2) + rb) * N + n0 + cb * 4); \
    } }

#define STOREB(BUF) { \
    unsigned int* dA = sA + (BUF) * (128 * 20); \
    unsigned int* dB = sB + (BUF) * (16 * 136); \
    _Pragma("unroll") \
    for (int it = 0; it < 2; ++it) { \
        int f = tid + it * 256; \
        int ra = f >> 2, ca = f & 3; \
        *(uint4*)&dA[ra * 20 + ca * 4] = va[it]; \
        int rb = f >> 5, cb = f & 31; \
        *(uint4*)&dB[rb * 136 + cb * 4] = vb[it]; \
    } }

    LOADG(0); STOREB(0); __syncthreads();

    for (int ch = 0; ch < nch; ++ch) {
        if (ch + 1 < nch) LOADG((ch + 1) * 16);
        const unsigned int* bA = sA + (ch & 1) * (128 * 20);
        const unsigned int* bB = sB + (ch & 1) * (16 * 136);
#pragma unroll
        for (int kq = 0; kq < 2; ++kq) {
            int kb = kq * 8;
            unsigned int ar[4][4];
#pragma unroll
            for (int mi = 0; mi < 4; ++mi) {
                int r = wm + mi * 16 + grp;
                ar[mi][0] = bA[r * 20 + kb + qd];
                ar[mi][1] = bA[(r + 8) * 20 + kb + qd];
                ar[mi][2] = bA[r * 20 + kb + qd + 4];
                ar[mi][3] = bA[(r + 8) * 20 + kb + qd + 4];
            }
            unsigned int br[4][2];
#pragma unroll
            for (int ni = 0; ni < 4; ++ni) {
                int n = wn + ni * 8 + grp;
                br[ni][0] = bB[(kb + qd) * 136 + n];
                br[ni][1] = bB[(kb + qd + 4) * 136 + n];
            }
#pragma unroll
            for (int mi = 0; mi < 4; ++mi)
#pragma unroll
                for (int ni = 0; ni < 4; ++ni)
                    mma16h(acc[mi][ni], ar[mi][0],ar[mi][1],ar[mi][2],ar[mi][3],
                           br[ni][0], br[ni][1]);
        }
        if (ch + 1 < nch) STOREB((ch + 1) & 1);
        __syncthreads();
    }
#undef LOADG
#undef STOREB

    if (MODE == 1) {
#pragma unroll
        for (int mi = 0; mi < 4; ++mi)
#pragma unroll
            for (int half = 0; half < 2; ++half) {
                int r = m0 + wm + mi * 16 + grp + half * 8;
                float ds = 0.0f;
#pragma unroll
                for (int ni = 0; ni < 4; ++ni) {
                    int col = n0 + wn + ni * 8 + qd * 2;
                    float v0 = tanhf(acc[mi][ni][half*2+0] + bias[col]);
                    float v1 = tanhf(acc[mi][ni][half*2+1] + bias[col+1]);
                    Hout[((size_t)r * HH + col) >> 1] = h2pack(v0, v1);
                    float2 sv = *(const float2*)&S[(size_t)r * HH + col];
                    ds = fmaf(1.0f - v0*v0, sv.x, ds);
                    ds = fmaf(1.0f - v1*v1, sv.y, ds);
                }
                ds += __shfl_xor_sync(0xffffffffu, ds, 1);
                ds += __shfl_xor_sync(0xffffffffu, ds, 2);
                if (qd == 0) atomicAdd(&rowsum[wm + mi*16 + grp + half*8], ds);
            }
        __syncthreads();
        if (tid < 128) atomicAdd(&accd[m0 + tid], wq * rowsum[tid]);
    } else {
#pragma unroll
        for (int mi = 0; mi < 4; ++mi)
#pragma unroll
            for (int half = 0; half < 2; ++half) {
                int r = m0 + wm + mi * 16 + grp + half * 8;
#pragma unroll
                for (int ni = 0; ni < 4; ++ni) {
                    int col = n0 + wn + ni * 8 + qd * 2;
                    float f0 = acc[mi][ni][half*2+0] + bias[col];
                    float f1 = acc[mi][ni][half*2+1] + bias[col+1];
                    size_t idx = (size_t)r * DD + col;
                    float2 az;
                    if (st == 0) az = make_float2(0.f, 0.f);
                    else az = *(float2*)&accz[idx];
                    az.x += wq * f0; az.y += wq * f1;
                    *(float2*)&accz[idx] = az;
                    if (st < 3) {
                        float2 xx = *(const float2*)&x[idx];
                        z[idx >> 1] = h2pack(xx.x + cq*f0, xx.y + cq*f1);
                    }
                }
            }
    }
}

// ---------------- final ----------------
__global__ __launch_bounds__(256) void final_kernel(const float* __restrict__ x,
                                                    float* __restrict__ out) {
    int i = blockIdx.x * 256 + threadIdx.x;
    const int half = BB * 257;
    if (i >= 2 * half) return;
    if (i < half) {
        int r = i / 257, d = i - r * 257;
        out[i] = (d < 256) ? x[r * DD + d] : 0.0f;
    } else {
        int j = i - half;
        int r = j / 257, d = j - r * 257;
        out[i] = (d < 256) ? x[r * DD + d] + g_accz[r * DD + d] * (1.0f / 6.0f)
                           : -g_accd[r] * (1.0f / 6.0f);
    }
}

// ---------------- launch (multi-stream overlapped DAG) ----------------
extern "C" void kernel_launch(void* const* d_in, const int* in_sizes, int n_in,
                              void* d_out, int out_size) {
    const float* x  = (const float*)d_in[0];
    const float* W1 = (const float*)d_in[1];
    const float* b1 = (const float*)d_in[2];
    const float* W2 = (const float*)d_in[3];
    const float* b2 = (const float*)d_in[4];
    float* out = (float*)d_out;
    (void)in_sizes; (void)n_in; (void)out_size;

    unsigned int kk[4][2];
    for (unsigned int st = 0; st < 4; ++st) {
        unsigned int f0, f1;
        tf_host(0u, 42u, 0u, st, f0, f1);
        tf_host(f0, f1, 0u, 1u, kk[st][0], kk[st][1]);
    }

    float *gbias, *gS, *gaccd, *gaccz;
    uint32_t *gxh, *gzh, *ghh, *gW1p, *gW2p;
    cudaGetSymbolAddress((void**)&gbias, g_bias1);
    cudaGetSymbolAddress((void**)&gS,    g_S);
    cudaGetSymbolAddress((void**)&gaccd, g_accd);
    cudaGetSymbolAddress((void**)&gaccz, g_accz);
    cudaGetSymbolAddress((void**)&gxh,   g_xh);
    cudaGetSymbolAddress((void**)&gzh,   g_zh);
    cudaGetSymbolAddress((void**)&ghh,   g_hh);
    cudaGetSymbolAddress((void**)&gW1p,  g_W1p);
    cudaGetSymbolAddress((void**)&gW2p,  g_W2p);

    cudaFuncSetAttribute(s_kernel, cudaFuncAttributeMaxDynamicSharedMemorySize, SK_SMEM);
    cudaFuncSetAttribute(gemm_kernel<0>, cudaFuncAttributeMaxDynamicSharedMemorySize, GEMM_SMEM);
    cudaFuncSetAttribute(gemm_kernel<1>, cudaFuncAttributeMaxDynamicSharedMemorySize, GEMM_SMEM);

    // Streams/events: created once on the FIRST (uncaptured) call; reused
    // inside capture thereafter. All forks rejoin the origin stream.
    static cudaStream_t sB = nullptr, sC = nullptr;
    static cudaEvent_t evPrep = nullptr, evRng[4], evS[4];
    if (!sB) {
        cudaStreamCreateWithFlags(&sB, cudaStreamNonBlocking);
        cudaStreamCreateWithFlags(&sC, cudaStreamNonBlocking);
        cudaEventCreateWithFlags(&evPrep, cudaEventDisableTiming);
        for (int i = 0; i < 4; ++i) {
            cudaEventCreateWithFlags(&evRng[i], cudaEventDisableTiming);
            cudaEventCreateWithFlags(&evS[i], cudaEventDisableTiming);
        }
    }

    // main stream: prep (bias/W2t/packed tables)
    prep_kernel<<<(BB*DD/2 + 255) / 256, 256>>>(x, W1, b1, W2);
    cudaEventRecord(evPrep, 0);

    // stream C: all RNG stages (ALU-bound, overlaps tensor work)
    cudaStreamWaitEvent(sC, evPrep, 0);
    for (int st = 0; st < 4; ++st) {
        rng_kernel<<<NE / 256, 256, 0, sC>>>(kk[st][0], kk[st][1], st);
        cudaEventRecord(evRng[st], sC);
    }

    // stream B: s_kernel per stage, gated on its RNG
    cudaStreamWaitEvent(sB, evPrep, 0);
    for (int st = 0; st < 4; ++st) {
        cudaStreamWaitEvent(sB, evRng[st], 0);
        s_kernel<<<dim3(BB / 64, HH / 64), 256, SK_SMEM, sB>>>(W1, st);
        cudaEventRecord(evS[st], sB);
    }

    // main stream: RK4 chain, each stage gated on its S tile
    const float wst[4] = {1.0f, 2.0f, 2.0f, 1.0f};
    const float cst[4] = {0.5f, 0.5f, 1.0f, 0.0f};
    for (int st = 0; st < 4; ++st) {
        cudaStreamWaitEvent(0, evS[st], 0);
        const uint32_t* Ain = (st == 0) ? gxh : gzh;
        gemm_kernel<1><<<dim3(BB/128, HH/128), 256, GEMM_SMEM>>>(
            Ain, gW1p, gbias + st*HH, ghh,
            gS + (size_t)st * BB * HH, gaccd,
            nullptr, nullptr, nullptr,
            HH, DD, st, wst[st], cst[st]);
        gemm_kernel<0><<<dim3(BB/128, DD/128), 256, GEMM_SMEM>>>(
            ghh, gW2p, b2, nullptr,
            nullptr, nullptr,
            x, gaccz, gzh,
            DD, HH, st, wst[st], cst[st]);
    }
    final_kernel<<<(2*BB*257 + 255)/256, 256>>>(x, out);
}